// round 4
// baseline (speedup 1.0000x reference)
#include <cuda_runtime.h>
#include <cstring>
#include <cmath>

// ============================================================================
// CPAB activation (difw Tessellation, NC=16 cells, RADIUS=3, 10x5 integration)
//
// out[n,c] = f_c(x[n,c]) where f_c is piecewise-LINEAR in x0. Strategy:
//   1) host: B_BASIS = last 15 rows of Q from Householder LQ of the 17x32
//      constraint matrix (matches numpy dgesdd Path 4t null-space rows).
//   2) gpu:  build per-channel LUT of f_c with the exact reference
//      integrator, stored as (y_i, y_{i+1}) float2 pairs (one LDS.64/lookup).
//   3) gpu:  float4-vectorized single-wave streaming lerp pass
//      (8 ch/block, 512 thr/block, pair-LUT in smem).
// ============================================================================

#define M_SAMP      512
#define CH_PER_BLK  8
#define MAX_C       256

struct BParam { float B[32][15]; };

// Pair table: 256 channels x M_SAMP intervals of (y_i, y_{i+1}).
__device__ float2 g_tab2[MAX_C * M_SAMP];

// ----------------------------------------------------------------------------
// Host: B_BASIS via Householder LQ (float64), matching LAPACK DGELQF/DORGLQ.
// ----------------------------------------------------------------------------
static void compute_basis(float Bout[32][15]) {
    const int nc = 16;
    const int m = nc + 1;      // 17
    const int n = 2 * nc;      // 32
    double A[17][32];
    std::memset(A, 0, sizeof(A));
    for (int k = 1; k < nc; k++) {
        double xk = (double)k / (double)nc;
        A[k - 1][2 * (k - 1)]     =  xk;
        A[k - 1][2 * (k - 1) + 1] =  1.0;
        A[k - 1][2 * k]           = -xk;
        A[k - 1][2 * k + 1]       = -1.0;
    }
    A[nc - 1][1]         = 1.0;
    A[nc][2 * (nc - 1)]  = 1.0;
    A[nc][2 * nc - 1]    = 1.0;

    double tau[17];
    for (int i = 0; i < m; i++) {
        double xn2 = 0.0;
        for (int j = i + 1; j < n; j++) xn2 += A[i][j] * A[i][j];
        double alpha = A[i][i];
        if (xn2 == 0.0) { tau[i] = 0.0; continue; }
        double beta = -copysign(sqrt(alpha * alpha + xn2), alpha);
        tau[i] = (beta - alpha) / beta;
        double s = 1.0 / (alpha - beta);
        for (int j = i + 1; j < n; j++) A[i][j] *= s;
        A[i][i] = beta;
        for (int r = i + 1; r < m; r++) {
            double w = A[r][i];
            for (int j = i + 1; j < n; j++) w += A[r][j] * A[i][j];
            w *= tau[i];
            A[r][i] -= w;
            for (int j = i + 1; j < n; j++) A[r][j] -= w * A[i][j];
        }
    }
    for (int t = 0; t < 15; t++) {
        double q[32];
        for (int j = 0; j < n; j++) q[j] = 0.0;
        q[m + t] = 1.0;
        for (int i = m - 1; i >= 0; i--) {
            if (tau[i] == 0.0) continue;
            double w = q[i];
            for (int j = i + 1; j < n; j++) w += A[i][j] * q[j];
            w *= tau[i];
            q[i] -= w;
            for (int j = i + 1; j < n; j++) q[j] -= w * A[i][j];
        }
        for (int j = 0; j < n; j++) Bout[j][t] = (float)q[j];
    }
}

// ----------------------------------------------------------------------------
// Device
// ----------------------------------------------------------------------------
__device__ __forceinline__ int cellf(float x) {
    int c = __float2int_rd(x * 16.0f);
    return min(max(c, 0), 15);
}

// One block per channel: a,b from theta @ B^T, exact reference integration
// at M_SAMP+1 grid points, emitted as float2 pairs. Also theta passthrough.
__global__ void build_tab_kernel(const float* __restrict__ theta,
                                 const int* __restrict__ time_p,
                                 float* __restrict__ theta_out,
                                 BParam Bp) {
    __shared__ float sa[16], sb[16], sE[16], sK[16];
    __shared__ float sy[M_SAMP + 1];
    int c = blockIdx.x;
    int tid = threadIdx.x;

    if (tid < 32) {
        float acc = 0.0f;
        #pragma unroll
        for (int t = 0; t < 15; t++) acc += theta[c * 15 + t] * Bp.B[tid][t];
        if (tid & 1) sb[tid >> 1] = acc;
        else         sa[tid >> 1] = acc;
    }
    if (tid >= 32 && tid < 32 + 15)
        theta_out[c * 15 + (tid - 32)] = theta[c * 15 + (tid - 32)];
    __syncthreads();

    float tm  = (float)(*time_p);
    float dt  = tm / 10.0f;
    float ddt = dt / 5.0f;

    if (tid < 16) {
        float a = sa[tid], b = sb[tid];
        float eta = expf(dt * a);
        bool  nz  = fabsf(a) > 1e-7f;
        sE[tid] = nz ? eta : 1.0f;
        sK[tid] = nz ? (b / a) * (eta - 1.0f) : b * dt;
    }
    __syncthreads();

    for (int i = tid; i <= M_SAMP; i += blockDim.x) {
        float phi = (float)i / (float)M_SAMP;
        #pragma unroll 1
        for (int s = 0; s < 10; s++) {
            int   c0 = cellf(phi);
            float pc = fmaf(sE[c0], phi, sK[c0]);
            if (cellf(pc) == c0) {
                phi = pc;
            } else {
                float p = phi;
                #pragma unroll
                for (int e = 0; e < 5; e++) {
                    int   cc = cellf(p);
                    float v  = fmaf(sa[cc], p, sb[cc]);
                    p = fmaf(ddt, v, p);
                }
                phi = p;
            }
        }
        sy[i] = fmaf(phi, 6.0f, -3.0f);
    }
    __syncthreads();

    for (int i = tid; i < M_SAMP; i += blockDim.x)
        g_tab2[c * M_SAMP + i] = make_float2(sy[i], sy[i + 1]);
}

// ----------------------------------------------------------------------------
// Main pass: float4 LDG/STG, one LDS.64 lerp per element.
// Block: 8 channels, 512 threads; thread (q = tid&1, row = tid>>1).
// ----------------------------------------------------------------------------
__device__ __forceinline__ float lerp_tab(const float2* __restrict__ tb, float xv) {
    float xs = (xv + 3.0f) * (1.0f / 6.0f);
    if (xs >= 1.0f || xs <= 0.0f) return xv;
    float t = xs * (float)M_SAMP;
    int   i = min((int)t, M_SAMP - 1);
    float fr = t - (float)i;
    float2 y = tb[i];
    return fmaf(y.y - y.x, fr, y.x);
}

__global__ void __launch_bounds__(512) cpab_main_kernel(
        const float4* __restrict__ x4,
        float4* __restrict__ out4,
        int N, int C4) {
    __shared__ float2 s_tab[CH_PER_BLK * M_SAMP];   // 32 KB

    int c0 = blockIdx.x * CH_PER_BLK;
    {   // table copy via float4 for fewer instructions
        const float4* src = (const float4*)(g_tab2 + c0 * M_SAMP);
        float4*       dst = (float4*)s_tab;
        for (int i = threadIdx.x; i < CH_PER_BLK * M_SAMP / 2; i += blockDim.x)
            dst[i] = src[i];
    }
    __syncthreads();

    int q   = threadIdx.x & 1;                  // which float4 of the 8 ch
    int row = threadIdx.x >> 1;                 // 0..255
    const float2* tb = s_tab + q * 4 * M_SAMP;

    int vbase = blockIdx.x * 2 + q;             // float4 column index

    int rows_per = (N + gridDim.y - 1) / gridDim.y;
    int r0 = blockIdx.y * rows_per;
    int r1 = min(r0 + rows_per, N);

    #pragma unroll 4
    for (int r = r0 + row; r < r1; r += 256) {
        size_t idx = (size_t)r * C4 + vbase;
        float4 v = __ldcs(&x4[idx]);
        float4 o;
        o.x = lerp_tab(tb + 0 * M_SAMP, v.x);
        o.y = lerp_tab(tb + 1 * M_SAMP, v.y);
        o.z = lerp_tab(tb + 2 * M_SAMP, v.z);
        o.w = lerp_tab(tb + 3 * M_SAMP, v.w);
        __stcs(&out4[idx], o);
    }
}

// ----------------------------------------------------------------------------
// Launch: inputs = [x, edge_index, edge_attr, batch, time, theta]
// output = concat(out[N,C], theta[C,15]) as float32
// ----------------------------------------------------------------------------
extern "C" void kernel_launch(void* const* d_in, const int* in_sizes, int n_in,
                              void* d_out, int out_size) {
    const float* x      = (const float*)d_in[0];
    const int*   time_p = (const int*)d_in[4];
    const float* theta  = (const float*)d_in[5];

    int C = in_sizes[5] / 15;   // 256
    int N = in_sizes[0] / C;    // 131072

    BParam Bp;
    compute_basis(Bp.B);

    build_tab_kernel<<<C, 256>>>(theta, time_p,
                                 (float*)d_out + (size_t)N * C, Bp);

    // Single wave: 4 blocks/SM (512 thr, 32 KB smem) x 148 SMs = 592.
    // 32 x 18 = 576 blocks <= 592.
    dim3 grid(C / CH_PER_BLK, 18);
    cpab_main_kernel<<<grid, 512>>>((const float4*)x, (float4*)d_out,
                                    N, C / 4);
}

// round 5
// speedup vs baseline: 1.5888x; 1.5888x over previous
#include <cuda_runtime.h>
#include <cstring>
#include <cmath>

// ============================================================================
// CPAB activation (difw Tessellation, NC=16 cells, RADIUS=3, 10x5 integration)
//
// out[n,c] = f_c(x[n,c]) where f_c is piecewise-LINEAR in x0. Strategy:
//   1) host: B_BASIS = last 15 rows of Q from Householder LQ of the 17x32
//      constraint matrix (matches numpy dgesdd Path 4t null-space rows).
//   2) gpu:  build per-channel scalar LUT of f_c with the exact reference
//      integrator (M_SAMP=512 intervals).
//   3) gpu:  float4-vectorized single-wave streaming lerp pass.
//      Scalar table => lookups are 2 independent LDS.32 spread over all 32
//      banks (the R4 float2 pair table aliased to even banks only — 2x
//      conflicts). Odd channel stride (513) decorrelates channel bases.
// ============================================================================

#define M_SAMP      512
#define TAB_W       (M_SAMP + 1)          // 513, odd stride
#define CH_PER_BLK  8
#define MAX_C       256

struct BParam { float B[32][15]; };

__device__ float g_tab[MAX_C * TAB_W];

// ----------------------------------------------------------------------------
// Host: B_BASIS via Householder LQ (float64), matching LAPACK DGELQF/DORGLQ.
// ----------------------------------------------------------------------------
static void compute_basis(float Bout[32][15]) {
    const int nc = 16;
    const int m = nc + 1;      // 17
    const int n = 2 * nc;      // 32
    double A[17][32];
    std::memset(A, 0, sizeof(A));
    for (int k = 1; k < nc; k++) {
        double xk = (double)k / (double)nc;
        A[k - 1][2 * (k - 1)]     =  xk;
        A[k - 1][2 * (k - 1) + 1] =  1.0;
        A[k - 1][2 * k]           = -xk;
        A[k - 1][2 * k + 1]       = -1.0;
    }
    A[nc - 1][1]         = 1.0;
    A[nc][2 * (nc - 1)]  = 1.0;
    A[nc][2 * nc - 1]    = 1.0;

    double tau[17];
    for (int i = 0; i < m; i++) {
        double xn2 = 0.0;
        for (int j = i + 1; j < n; j++) xn2 += A[i][j] * A[i][j];
        double alpha = A[i][i];
        if (xn2 == 0.0) { tau[i] = 0.0; continue; }
        double beta = -copysign(sqrt(alpha * alpha + xn2), alpha);
        tau[i] = (beta - alpha) / beta;
        double s = 1.0 / (alpha - beta);
        for (int j = i + 1; j < n; j++) A[i][j] *= s;
        A[i][i] = beta;
        for (int r = i + 1; r < m; r++) {
            double w = A[r][i];
            for (int j = i + 1; j < n; j++) w += A[r][j] * A[i][j];
            w *= tau[i];
            A[r][i] -= w;
            for (int j = i + 1; j < n; j++) A[r][j] -= w * A[i][j];
        }
    }
    for (int t = 0; t < 15; t++) {
        double q[32];
        for (int j = 0; j < n; j++) q[j] = 0.0;
        q[m + t] = 1.0;
        for (int i = m - 1; i >= 0; i--) {
            if (tau[i] == 0.0) continue;
            double w = q[i];
            for (int j = i + 1; j < n; j++) w += A[i][j] * q[j];
            w *= tau[i];
            q[i] -= w;
            for (int j = i + 1; j < n; j++) q[j] -= w * A[i][j];
        }
        for (int j = 0; j < n; j++) Bout[j][t] = (float)q[j];
    }
}

// ----------------------------------------------------------------------------
// Device
// ----------------------------------------------------------------------------
__device__ __forceinline__ int cellf(float x) {
    int c = __float2int_rd(x * 16.0f);
    return min(max(c, 0), 15);
}

// One block per channel: a,b from theta @ B^T, exact reference integration
// at TAB_W grid points. Also emits the theta passthrough rows.
__global__ void build_tab_kernel(const float* __restrict__ theta,
                                 const int* __restrict__ time_p,
                                 float* __restrict__ theta_out,
                                 BParam Bp) {
    __shared__ float sa[16], sb[16], sE[16], sK[16];
    int c = blockIdx.x;
    int tid = threadIdx.x;

    if (tid < 32) {
        float acc = 0.0f;
        #pragma unroll
        for (int t = 0; t < 15; t++) acc += theta[c * 15 + t] * Bp.B[tid][t];
        if (tid & 1) sb[tid >> 1] = acc;
        else         sa[tid >> 1] = acc;
    }
    if (tid >= 32 && tid < 32 + 15)
        theta_out[c * 15 + (tid - 32)] = theta[c * 15 + (tid - 32)];
    __syncthreads();

    float tm  = (float)(*time_p);
    float dt  = tm / 10.0f;
    float ddt = dt / 5.0f;

    if (tid < 16) {
        float a = sa[tid], b = sb[tid];
        float eta = expf(dt * a);
        bool  nz  = fabsf(a) > 1e-7f;
        sE[tid] = nz ? eta : 1.0f;
        sK[tid] = nz ? (b / a) * (eta - 1.0f) : b * dt;
    }
    __syncthreads();

    for (int i = tid; i <= M_SAMP; i += blockDim.x) {
        float phi = (float)i / (float)M_SAMP;
        #pragma unroll 1
        for (int s = 0; s < 10; s++) {
            int   c0 = cellf(phi);
            float pc = fmaf(sE[c0], phi, sK[c0]);
            if (cellf(pc) == c0) {
                phi = pc;
            } else {
                float p = phi;
                #pragma unroll
                for (int e = 0; e < 5; e++) {
                    int   cc = cellf(p);
                    float v  = fmaf(sa[cc], p, sb[cc]);
                    p = fmaf(ddt, v, p);
                }
                phi = p;
            }
        }
        g_tab[c * TAB_W + i] = fmaf(phi, 6.0f, -3.0f);
    }
}

// ----------------------------------------------------------------------------
// Main pass: float4 LDG/STG; per element two independent LDS.32 (full 32-bank
// spread) + lerp. Block: 8 channels, 512 threads, single wave over the grid.
// ----------------------------------------------------------------------------
__device__ __forceinline__ float lerp_tab(const float* __restrict__ tb, float xv) {
    float xs = (xv + 3.0f) * (1.0f / 6.0f);
    if (xs >= 1.0f || xs <= 0.0f) return xv;
    float t = xs * (float)M_SAMP;
    int   i = min((int)t, M_SAMP - 1);
    float fr = t - (float)i;
    float y0 = tb[i];
    float y1 = tb[i + 1];
    return fmaf(y1 - y0, fr, y0);
}

__global__ void __launch_bounds__(512, 4) cpab_main_kernel(
        const float4* __restrict__ x4,
        float4* __restrict__ out4,
        int N, int C4) {
    __shared__ float s_tab[CH_PER_BLK * TAB_W];   // 16.4 KB

    int c0 = blockIdx.x * CH_PER_BLK;
    for (int i = threadIdx.x; i < CH_PER_BLK * TAB_W; i += blockDim.x)
        s_tab[i] = g_tab[c0 * TAB_W + i];
    __syncthreads();

    int q   = threadIdx.x & 1;                    // which float4 of the 8 ch
    int row = threadIdx.x >> 1;                   // 0..255
    const float* tb = s_tab + q * 4 * TAB_W;

    int vbase = blockIdx.x * 2 + q;               // float4 column index

    int rows_per = (N + gridDim.y - 1) / gridDim.y;
    int r0 = blockIdx.y * rows_per;
    int r1 = min(r0 + rows_per, N);

    #pragma unroll 4
    for (int r = r0 + row; r < r1; r += 256) {
        size_t idx = (size_t)r * C4 + vbase;
        float4 v = __ldcs(&x4[idx]);
        float4 o;
        o.x = lerp_tab(tb + 0 * TAB_W, v.x);
        o.y = lerp_tab(tb + 1 * TAB_W, v.y);
        o.z = lerp_tab(tb + 2 * TAB_W, v.z);
        o.w = lerp_tab(tb + 3 * TAB_W, v.w);
        __stcs(&out4[idx], o);
    }
}

// ----------------------------------------------------------------------------
// Launch: inputs = [x, edge_index, edge_attr, batch, time, theta]
// output = concat(out[N,C], theta[C,15]) as float32
// ----------------------------------------------------------------------------
extern "C" void kernel_launch(void* const* d_in, const int* in_sizes, int n_in,
                              void* d_out, int out_size) {
    const float* x      = (const float*)d_in[0];
    const int*   time_p = (const int*)d_in[4];
    const float* theta  = (const float*)d_in[5];

    int C = in_sizes[5] / 15;   // 256
    int N = in_sizes[0] / C;    // 131072

    BParam Bp;
    compute_basis(Bp.B);

    build_tab_kernel<<<C, 256>>>(theta, time_p,
                                 (float*)d_out + (size_t)N * C, Bp);

    // Single wave: 4 blocks/SM (512 thr, 16.4 KB smem, 32 regs) x 148 SMs
    // = 592 slots; grid 32 x 18 = 576 blocks.
    dim3 grid(C / CH_PER_BLK, 18);
    cpab_main_kernel<<<grid, 512>>>((const float4*)x, (float4*)d_out,
                                    N, C / 4);
}

// round 6
// speedup vs baseline: 1.7341x; 1.0914x over previous
#include <cuda_runtime.h>
#include <cuda_fp16.h>
#include <cstring>
#include <cmath>

// ============================================================================
// CPAB activation (difw Tessellation, NC=16 cells, RADIUS=3, 10x5 integration)
//
// out[n,c] = f_c(x[n,c]) where f_c is piecewise-LINEAR in x0. Strategy:
//   1) host: B_BASIS = last 15 rows of Q from Householder LQ of the 17x32
//      constraint matrix (matches numpy dgesdd Path 4t null-space rows).
//   2) gpu:  build per-channel LUT with the exact reference integrator,
//      stored as half2 (d_i, d_{i+1}) where d(i) = f(X_i) - X_i is the
//      displacement. Since lerp over nodes X(i) reproduces xv exactly,
//      out = xv + lerp(d0, d1)  -> ONE LDS.32 per element (was 2).
//   3) gpu:  float4-vectorized single-wave streaming lerp pass.
// ============================================================================

#define M_SAMP      512
#define TAB_W       (M_SAMP + 1)          // word stride per channel (odd)
#define CH_PER_BLK  8
#define MAX_C       256

struct BParam { float B[32][15]; };

// Packed displacement table: word i of channel c = half2(d_i, d_{i+1}).
__device__ __half2 g_tabh[MAX_C * TAB_W];

// ----------------------------------------------------------------------------
// Host: B_BASIS via Householder LQ (float64), matching LAPACK DGELQF/DORGLQ.
// ----------------------------------------------------------------------------
static void compute_basis(float Bout[32][15]) {
    const int nc = 16;
    const int m = nc + 1;      // 17
    const int n = 2 * nc;      // 32
    double A[17][32];
    std::memset(A, 0, sizeof(A));
    for (int k = 1; k < nc; k++) {
        double xk = (double)k / (double)nc;
        A[k - 1][2 * (k - 1)]     =  xk;
        A[k - 1][2 * (k - 1) + 1] =  1.0;
        A[k - 1][2 * k]           = -xk;
        A[k - 1][2 * k + 1]       = -1.0;
    }
    A[nc - 1][1]         = 1.0;
    A[nc][2 * (nc - 1)]  = 1.0;
    A[nc][2 * nc - 1]    = 1.0;

    double tau[17];
    for (int i = 0; i < m; i++) {
        double xn2 = 0.0;
        for (int j = i + 1; j < n; j++) xn2 += A[i][j] * A[i][j];
        double alpha = A[i][i];
        if (xn2 == 0.0) { tau[i] = 0.0; continue; }
        double beta = -copysign(sqrt(alpha * alpha + xn2), alpha);
        tau[i] = (beta - alpha) / beta;
        double s = 1.0 / (alpha - beta);
        for (int j = i + 1; j < n; j++) A[i][j] *= s;
        A[i][i] = beta;
        for (int r = i + 1; r < m; r++) {
            double w = A[r][i];
            for (int j = i + 1; j < n; j++) w += A[r][j] * A[i][j];
            w *= tau[i];
            A[r][i] -= w;
            for (int j = i + 1; j < n; j++) A[r][j] -= w * A[i][j];
        }
    }
    for (int t = 0; t < 15; t++) {
        double q[32];
        for (int j = 0; j < n; j++) q[j] = 0.0;
        q[m + t] = 1.0;
        for (int i = m - 1; i >= 0; i--) {
            if (tau[i] == 0.0) continue;
            double w = q[i];
            for (int j = i + 1; j < n; j++) w += A[i][j] * q[j];
            w *= tau[i];
            q[i] -= w;
            for (int j = i + 1; j < n; j++) q[j] -= w * A[i][j];
        }
        for (int j = 0; j < n; j++) Bout[j][t] = (float)q[j];
    }
}

// ----------------------------------------------------------------------------
// Device
// ----------------------------------------------------------------------------
__device__ __forceinline__ int cellf(float x) {
    int c = __float2int_rd(x * 16.0f);
    return min(max(c, 0), 15);
}

// One block per channel: a,b from theta @ B^T, exact reference integration
// at M_SAMP+1 grid points; emits half2 displacement pairs + theta rows.
__global__ void build_tab_kernel(const float* __restrict__ theta,
                                 const int* __restrict__ time_p,
                                 float* __restrict__ theta_out,
                                 BParam Bp) {
    __shared__ float sa[16], sb[16], sE[16], sK[16];
    __shared__ float sd[M_SAMP + 1];        // displacements d_i (fp32)
    int c = blockIdx.x;
    int tid = threadIdx.x;

    if (tid < 32) {
        float acc = 0.0f;
        #pragma unroll
        for (int t = 0; t < 15; t++) acc += theta[c * 15 + t] * Bp.B[tid][t];
        if (tid & 1) sb[tid >> 1] = acc;
        else         sa[tid >> 1] = acc;
    }
    if (tid >= 32 && tid < 32 + 15)
        theta_out[c * 15 + (tid - 32)] = theta[c * 15 + (tid - 32)];
    __syncthreads();

    float tm  = (float)(*time_p);
    float dt  = tm / 10.0f;
    float ddt = dt / 5.0f;

    if (tid < 16) {
        float a = sa[tid], b = sb[tid];
        float eta = expf(dt * a);
        bool  nz  = fabsf(a) > 1e-7f;
        sE[tid] = nz ? eta : 1.0f;
        sK[tid] = nz ? (b / a) * (eta - 1.0f) : b * dt;
    }
    __syncthreads();

    for (int i = tid; i <= M_SAMP; i += blockDim.x) {
        float phi = (float)i / (float)M_SAMP;
        float x0  = phi;
        #pragma unroll 1
        for (int s = 0; s < 10; s++) {
            int   c0 = cellf(phi);
            float pc = fmaf(sE[c0], phi, sK[c0]);
            if (cellf(pc) == c0) {
                phi = pc;
            } else {
                float p = phi;
                #pragma unroll
                for (int e = 0; e < 5; e++) {
                    int   cc = cellf(p);
                    float v  = fmaf(sa[cc], p, sb[cc]);
                    p = fmaf(ddt, v, p);
                }
                phi = p;
            }
        }
        // y = phi*6 - 3 ; node X = x0*6 - 3 ; displacement d = (phi - x0)*6
        sd[i] = (phi - x0) * 6.0f;
    }
    __syncthreads();

    for (int i = tid; i < M_SAMP; i += blockDim.x)
        g_tabh[c * TAB_W + i] = __floats2half2_rn(sd[i], sd[i + 1]);
}

// ----------------------------------------------------------------------------
// Main pass: float4 LDG/STG; ONE LDS.32 (half2 pair) + lerp per element.
// Block: 8 channels, 512 threads, single wave over the grid.
// ----------------------------------------------------------------------------
__device__ __forceinline__ float lerp_tab(const __half2* __restrict__ tb, float xv) {
    float xs = (xv + 3.0f) * (1.0f / 6.0f);
    if (xs >= 1.0f || xs <= 0.0f) return xv;
    float t = xs * (float)M_SAMP;
    int   i = min((int)t, M_SAMP - 1);
    float fr = t - (float)i;
    float2 d = __half22float2(tb[i]);        // (d_i, d_{i+1})
    return xv + fmaf(d.y - d.x, fr, d.x);
}

__global__ void __launch_bounds__(512, 4) cpab_main_kernel(
        const float4* __restrict__ x4,
        float4* __restrict__ out4,
        int N, int C4) {
    __shared__ __half2 s_tab[CH_PER_BLK * TAB_W];   // 16.4 KB

    int c0 = blockIdx.x * CH_PER_BLK;
    {
        const float4* src = (const float4*)(g_tabh + c0 * TAB_W);
        float4*       dst = (float4*)s_tab;
        // copy 8*513 words = 1026 float4s (tail word handled separately)
        int nwords = CH_PER_BLK * TAB_W;
        for (int i = threadIdx.x; i < nwords / 4; i += blockDim.x)
            dst[i] = src[i];
        if (threadIdx.x < (nwords & 3))
            s_tab[(nwords & ~3) + threadIdx.x] =
                g_tabh[c0 * TAB_W + (nwords & ~3) + threadIdx.x];
    }
    __syncthreads();

    int q   = threadIdx.x & 1;                    // which float4 of the 8 ch
    int row = threadIdx.x >> 1;                   // 0..255
    const __half2* tb = s_tab + q * 4 * TAB_W;

    int vbase = blockIdx.x * 2 + q;               // float4 column index

    int rows_per = (N + gridDim.y - 1) / gridDim.y;
    int r0 = blockIdx.y * rows_per;
    int r1 = min(r0 + rows_per, N);

    #pragma unroll 4
    for (int r = r0 + row; r < r1; r += 256) {
        size_t idx = (size_t)r * C4 + vbase;
        float4 v = __ldcs(&x4[idx]);
        float4 o;
        o.x = lerp_tab(tb + 0 * TAB_W, v.x);
        o.y = lerp_tab(tb + 1 * TAB_W, v.y);
        o.z = lerp_tab(tb + 2 * TAB_W, v.z);
        o.w = lerp_tab(tb + 3 * TAB_W, v.w);
        __stcs(&out4[idx], o);
    }
}

// ----------------------------------------------------------------------------
// Launch: inputs = [x, edge_index, edge_attr, batch, time, theta]
// output = concat(out[N,C], theta[C,15]) as float32
// ----------------------------------------------------------------------------
extern "C" void kernel_launch(void* const* d_in, const int* in_sizes, int n_in,
                              void* d_out, int out_size) {
    const float* x      = (const float*)d_in[0];
    const int*   time_p = (const int*)d_in[4];
    const float* theta  = (const float*)d_in[5];

    int C = in_sizes[5] / 15;   // 256
    int N = in_sizes[0] / C;    // 131072

    BParam Bp;
    compute_basis(Bp.B);

    build_tab_kernel<<<C, 256>>>(theta, time_p,
                                 (float*)d_out + (size_t)N * C, Bp);

    // Single wave: 4 blocks/SM (512 thr, 16.4 KB smem, 32 regs) x 148 SMs
    // = 592 slots; grid 32 x 18 = 576 blocks.
    dim3 grid(C / CH_PER_BLK, 18);
    cpab_main_kernel<<<grid, 512>>>((const float4*)x, (float4*)d_out,
                                    N, C / 4);
}

// round 8
// speedup vs baseline: 2.1353x; 1.2314x over previous
#include <cuda_runtime.h>
#include <cuda_fp16.h>
#include <cstring>
#include <cmath>

// ============================================================================
// CPAB activation (difw Tessellation, NC=16 cells, RADIUS=3, 10x5 integration)
//
// out[n,c] = f_c(x[n,c]) where f_c is piecewise-LINEAR in x0. Strategy:
//   1) host: B_BASIS = last 15 rows of Q from Householder LQ of the 17x32
//      constraint matrix (matches numpy dgesdd Path 4t null-space rows).
//   2) gpu:  build per-channel LUT with the exact reference integrator,
//      stored as half2 (d_i, d_{i+1}) displacement pairs: out = xv + lerp(d).
//      -> ONE LDS.32 per element.
//   3) gpu:  float4 streaming pass. Block owns 32 channels = 128 BYTES PER
//      ROW, lane map (p=tid&7,row=tid>>3): every LDG.128/STG.128 warp op
//      covers 4 full 128B lines = 4 wavefronts (the old 8-channel block
//      touched 16 lines at 64B each = 16 wavefronts -> L1-bound).
//      1024 thr/block, 65.7KB dynamic smem, 2 blocks/SM, single wave.
// ============================================================================

#define M_SAMP      512
#define TAB_W       (M_SAMP + 1)          // word stride per channel (odd)
#define CH_PER_BLK  32
#define MAX_C       256

struct BParam { float B[32][15]; };

// Packed displacement table: word i of channel c = half2(d_i, d_{i+1}).
__device__ __half2 g_tabh[MAX_C * TAB_W];

// ----------------------------------------------------------------------------
// Host: B_BASIS via Householder LQ (float64), matching LAPACK DGELQF/DORGLQ.
// ----------------------------------------------------------------------------
static void compute_basis(float Bout[32][15]) {
    const int nc = 16;
    const int m = nc + 1;      // 17
    const int n = 2 * nc;      // 32
    double A[17][32];
    std::memset(A, 0, sizeof(A));
    for (int k = 1; k < nc; k++) {
        double xk = (double)k / (double)nc;
        A[k - 1][2 * (k - 1)]     =  xk;
        A[k - 1][2 * (k - 1) + 1] =  1.0;
        A[k - 1][2 * k]           = -xk;
        A[k - 1][2 * k + 1]       = -1.0;
    }
    A[nc - 1][1]         = 1.0;
    A[nc][2 * (nc - 1)]  = 1.0;
    A[nc][2 * nc - 1]    = 1.0;

    double tau[17];
    for (int i = 0; i < m; i++) {
        double xn2 = 0.0;
        for (int j = i + 1; j < n; j++) xn2 += A[i][j] * A[i][j];
        double alpha = A[i][i];
        if (xn2 == 0.0) { tau[i] = 0.0; continue; }
        double beta = -copysign(sqrt(alpha * alpha + xn2), alpha);
        tau[i] = (beta - alpha) / beta;
        double s = 1.0 / (alpha - beta);
        for (int j = i + 1; j < n; j++) A[i][j] *= s;
        A[i][i] = beta;
        for (int r = i + 1; r < m; r++) {
            double w = A[r][i];
            for (int j = i + 1; j < n; j++) w += A[r][j] * A[i][j];
            w *= tau[i];
            A[r][i] -= w;
            for (int j = i + 1; j < n; j++) A[r][j] -= w * A[i][j];
        }
    }
    for (int t = 0; t < 15; t++) {
        double q[32];
        for (int j = 0; j < n; j++) q[j] = 0.0;
        q[m + t] = 1.0;
        for (int i = m - 1; i >= 0; i--) {
            if (tau[i] == 0.0) continue;
            double w = q[i];
            for (int j = i + 1; j < n; j++) w += A[i][j] * q[j];
            w *= tau[i];
            q[i] -= w;
            for (int j = i + 1; j < n; j++) q[j] -= w * A[i][j];
        }
        for (int j = 0; j < n; j++) Bout[j][t] = (float)q[j];
    }
}

// ----------------------------------------------------------------------------
// Device
// ----------------------------------------------------------------------------
__device__ __forceinline__ int cellf(float x) {
    int c = __float2int_rd(x * 16.0f);
    return min(max(c, 0), 15);
}

// One block per channel: a,b from theta @ B^T, exact reference integration
// at M_SAMP+1 grid points; emits half2 displacement pairs + theta rows.
__global__ void build_tab_kernel(const float* __restrict__ theta,
                                 const int* __restrict__ time_p,
                                 float* __restrict__ theta_out,
                                 BParam Bp) {
    __shared__ float sa[16], sb[16], sE[16], sK[16];
    __shared__ float sd[M_SAMP + 1];        // displacements d_i (fp32)
    int c = blockIdx.x;
    int tid = threadIdx.x;

    if (tid < 32) {
        float acc = 0.0f;
        #pragma unroll
        for (int t = 0; t < 15; t++) acc += theta[c * 15 + t] * Bp.B[tid][t];
        if (tid & 1) sb[tid >> 1] = acc;
        else         sa[tid >> 1] = acc;
    }
    if (tid >= 32 && tid < 32 + 15)
        theta_out[c * 15 + (tid - 32)] = theta[c * 15 + (tid - 32)];
    __syncthreads();

    float tm  = (float)(*time_p);
    float dt  = tm / 10.0f;
    float ddt = dt / 5.0f;

    if (tid < 16) {
        float a = sa[tid], b = sb[tid];
        float eta = expf(dt * a);
        bool  nz  = fabsf(a) > 1e-7f;
        sE[tid] = nz ? eta : 1.0f;
        sK[tid] = nz ? (b / a) * (eta - 1.0f) : b * dt;
    }
    __syncthreads();

    for (int i = tid; i <= M_SAMP; i += blockDim.x) {
        float phi = (float)i / (float)M_SAMP;
        float x0  = phi;
        #pragma unroll 1
        for (int s = 0; s < 10; s++) {
            int   c0 = cellf(phi);
            float pc = fmaf(sE[c0], phi, sK[c0]);
            if (cellf(pc) == c0) {
                phi = pc;
            } else {
                float p = phi;
                #pragma unroll
                for (int e = 0; e < 5; e++) {
                    int   cc = cellf(p);
                    float v  = fmaf(sa[cc], p, sb[cc]);
                    p = fmaf(ddt, v, p);
                }
                phi = p;
            }
        }
        // y = phi*6 - 3 ; node X = x0*6 - 3 ; displacement d = (phi - x0)*6
        sd[i] = (phi - x0) * 6.0f;
    }
    __syncthreads();

    for (int i = tid; i < M_SAMP; i += blockDim.x)
        g_tabh[c * TAB_W + i] = __floats2half2_rn(sd[i], sd[i + 1]);
}

// ----------------------------------------------------------------------------
// Main pass: float4 LDG/STG (4 wavefronts/warp-op), one LDS.32 per element.
// Block: 32 channels, 1024 threads, dynamic smem table, single wave.
// ----------------------------------------------------------------------------
__device__ __forceinline__ float lerp_tab(const __half2* __restrict__ tb, float xv) {
    float xs = (xv + 3.0f) * (1.0f / 6.0f);
    if (xs >= 1.0f || xs <= 0.0f) return xv;
    float t = xs * (float)M_SAMP;
    int   i = min((int)t, M_SAMP - 1);
    float fr = t - (float)i;
    float2 d = __half22float2(tb[i]);        // (d_i, d_{i+1})
    return xv + fmaf(d.y - d.x, fr, d.x);
}

__global__ void __launch_bounds__(1024, 2) cpab_main_kernel(
        const float4* __restrict__ x4,
        float4* __restrict__ out4,
        int N, int C4) {
    extern __shared__ __half2 s_tab[];            // 32 * 513 * 4B = 65.7 KB

    int c0 = blockIdx.x * CH_PER_BLK;
    {
        const float4* src = (const float4*)(g_tabh + c0 * TAB_W);
        float4*       dst = (float4*)s_tab;
        int n4 = CH_PER_BLK * TAB_W / 4;          // 16416/4 = 4104, exact
        for (int i = threadIdx.x; i < n4; i += blockDim.x)
            dst[i] = src[i];
    }
    __syncthreads();

    int p   = threadIdx.x & 7;                    // which float4 of 32 ch
    int row = threadIdx.x >> 3;                   // 0..127
    const __half2* tb = s_tab + p * 4 * TAB_W;

    int vbase = blockIdx.x * 8 + p;               // float4 column index

    int rows_per = (N + gridDim.y - 1) / gridDim.y;
    int r0 = blockIdx.y * rows_per;
    int r1 = min(r0 + rows_per, N);

    #pragma unroll 4
    for (int r = r0 + row; r < r1; r += 128) {
        size_t idx = (size_t)r * C4 + vbase;
        float4 v = __ldcs(&x4[idx]);
        float4 o;
        o.x = lerp_tab(tb + 0 * TAB_W, v.x);
        o.y = lerp_tab(tb + 1 * TAB_W, v.y);
        o.z = lerp_tab(tb + 2 * TAB_W, v.z);
        o.w = lerp_tab(tb + 3 * TAB_W, v.w);
        __stcs(&out4[idx], o);
    }
}

// ----------------------------------------------------------------------------
// Launch: inputs = [x, edge_index, edge_attr, batch, time, theta]
// output = concat(out[N,C], theta[C,15]) as float32
// ----------------------------------------------------------------------------
extern "C" void kernel_launch(void* const* d_in, const int* in_sizes, int n_in,
                              void* d_out, int out_size) {
    const float* x      = (const float*)d_in[0];
    const int*   time_p = (const int*)d_in[4];
    const float* theta  = (const float*)d_in[5];

    int C = in_sizes[5] / 15;   // 256
    int N = in_sizes[0] / C;    // 131072

    BParam Bp;
    compute_basis(Bp.B);

    build_tab_kernel<<<C, 256>>>(theta, time_p,
                                 (float*)d_out + (size_t)N * C, Bp);

    const int smem_bytes = CH_PER_BLK * TAB_W * (int)sizeof(__half2); // 65664
    static bool attr_set = false;
    if (!attr_set) {
        cudaFuncSetAttribute(cpab_main_kernel,
                             cudaFuncAttributeMaxDynamicSharedMemorySize,
                             smem_bytes);
        attr_set = true;
    }

    // Single wave: 2 blocks/SM (1024 thr, 65.7 KB smem, 32 regs) x 148 SMs
    // = 296 slots; grid 8 x 37 = 296 blocks.
    dim3 grid(C / CH_PER_BLK, 37);
    cpab_main_kernel<<<grid, 1024, smem_bytes>>>((const float4*)x,
                                                 (float4*)d_out, N, C / 4);
}